// round 3
// baseline (speedup 1.0000x reference)
#include <cuda_runtime.h>
#include <cuda_bf16.h>
#include <cstdint>

#define NN  100000
#define EE  1200000
#define FIN 128
#define HID 64

// Scratch (static __device__ arrays — no allocation allowed)
__device__ __align__(256) float g_deg[NN];
__device__ __align__(256) float g_ys [(size_t)NN * HID];   // dinv-scaled features (gather source)
__device__ __align__(256) float g_acc[(size_t)NN * HID];   // aggregation accumulator
__device__ __align__(256) float g_s1[NN];                  // scalar layer source
__device__ __align__(256) float g_s2[NN];                  // scalar layer accumulator
__device__ int g_is64;

// ---------- edge dtype detection (int64 vs silently-demoted int32) ----------
__global__ void k_detect(const long long* ei, int e) {
    if (blockIdx.x == 0 && threadIdx.x == 0) {
        int ok = 1;
        int m = e < 64 ? e : 64;
        for (int i = 0; i < m; i++) {
            long long v = ei[i];
            if (v < 0 || v >= NN) { ok = 0; break; }
        }
        g_is64 = ok;
    }
}

__device__ __forceinline__ int edge_at(const void* ei, int is64, size_t idx) {
    if (is64) return (int)((const long long*)ei)[idx];
    return ((const int*)ei)[idx];
}

// ---------- degree ----------
__global__ void k_deg_init(int n) {
    int i = blockIdx.x * blockDim.x + threadIdx.x;
    if (i < n) g_deg[i] = 1.0f;   // self loop
}

__global__ void k_deg_count(const void* ei, int e) {
    int i = blockIdx.x * blockDim.x + threadIdx.x;
    if (i >= e) return;
    int is64 = g_is64;
    int dst = edge_at(ei, is64, (size_t)e + i);
    atomicAdd(&g_deg[dst], 1.0f);
}

// ---------- dense GEMM: rows x [K] @ W[K][64]  ->  ys = acc = (A@W)*dinv ----------
// FUSE: input A is g_acc from previous layer; apply h = relu(a*dinv + bias_in[k]) on load.
template <int K, bool FUSE>
__global__ __launch_bounds__(128)
void k_gemm(const float* A, const float* __restrict__ W,
            const float* __restrict__ bias_in, int n) {
    __shared__ float Wsm[K * HID];
    __shared__ float bsm[K];
    for (int i = threadIdx.x; i < K * HID; i += blockDim.x) Wsm[i] = W[i];
    if (FUSE) {
        for (int i = threadIdx.x; i < K; i += blockDim.x) bsm[i] = bias_in[i];
    }
    __syncthreads();

    int row = blockIdx.x * blockDim.x + threadIdx.x;
    if (row >= n) return;
    float dinv = rsqrtf(g_deg[row]);

    float acc[HID];
#pragma unroll
    for (int j = 0; j < HID; j++) acc[j] = 0.0f;

    const float4* Ar = reinterpret_cast<const float4*>(
        (FUSE ? g_acc : A) + (size_t)row * K);

#pragma unroll 2
    for (int k4 = 0; k4 < K / 4; k4++) {
        float4 a4 = Ar[k4];
        float av[4] = {a4.x, a4.y, a4.z, a4.w};
#pragma unroll
        for (int kk = 0; kk < 4; kk++) {
            float a = av[kk];
            if (FUSE) a = fmaxf(fmaf(a, dinv, bsm[k4 * 4 + kk]), 0.0f);
            const float4* wr =
                reinterpret_cast<const float4*>(&Wsm[(k4 * 4 + kk) * HID]);
#pragma unroll
            for (int j4 = 0; j4 < HID / 4; j4++) {
                float4 w = wr[j4];
                acc[j4 * 4 + 0] = fmaf(a, w.x, acc[j4 * 4 + 0]);
                acc[j4 * 4 + 1] = fmaf(a, w.y, acc[j4 * 4 + 1]);
                acc[j4 * 4 + 2] = fmaf(a, w.z, acc[j4 * 4 + 2]);
                acc[j4 * 4 + 3] = fmaf(a, w.w, acc[j4 * 4 + 3]);
            }
        }
    }

    float4* ys = reinterpret_cast<float4*>(g_ys  + (size_t)row * HID);
    float4* ac = reinterpret_cast<float4*>(g_acc + (size_t)row * HID);
#pragma unroll
    for (int j4 = 0; j4 < HID / 4; j4++) {
        float4 v;
        v.x = acc[j4 * 4 + 0] * dinv;
        v.y = acc[j4 * 4 + 1] * dinv;
        v.z = acc[j4 * 4 + 2] * dinv;
        v.w = acc[j4 * 4 + 3] * dinv;
        ys[j4] = v;   // gather source (dinv-scaled)
        ac[j4] = v;   // accumulator initialized with self-loop message
    }
}

// ---------- edge scatter: acc[dst] += ys[src], 64 floats, 16 threads/edge ----------
__global__ void k_scatter(const void* ei, int e) {
    int t = blockIdx.x * blockDim.x + threadIdx.x;
    int edge = t >> 4;
    if (edge >= e) return;
    int part = t & 15;
    int is64 = g_is64;
    int src = edge_at(ei, is64, (size_t)edge);
    int dst = edge_at(ei, is64, (size_t)e + edge);

    float4 v = reinterpret_cast<const float4*>(g_ys + (size_t)src * HID)[part];
    float* daddr = g_acc + (size_t)dst * HID + part * 4;
    asm volatile("red.global.add.v4.f32 [%0], {%1,%2,%3,%4};"
                 :: "l"(daddr), "f"(v.x), "f"(v.y), "f"(v.z), "f"(v.w)
                 : "memory");
}

// ---------- layer 2 (OUT=1): s1 = s2 = ((relu(acc*dinv + b1)) . W2) * dinv ----------
__global__ void k_gemm2(const float* __restrict__ b1,
                        const float* __restrict__ W2, int n) {
    int i = blockIdx.x * blockDim.x + threadIdx.x;
    if (i >= n) return;
    float dinv = rsqrtf(g_deg[i]);
    const float4* ar = reinterpret_cast<const float4*>(g_acc + (size_t)i * HID);
    const float4* br = reinterpret_cast<const float4*>(b1);
    const float4* wr = reinterpret_cast<const float4*>(W2);
    float s = 0.0f;
#pragma unroll
    for (int j4 = 0; j4 < HID / 4; j4++) {
        float4 a = ar[j4];
        float4 b = __ldg(&br[j4]);
        float4 w = __ldg(&wr[j4]);
        s += fmaxf(fmaf(a.x, dinv, b.x), 0.0f) * w.x;
        s += fmaxf(fmaf(a.y, dinv, b.y), 0.0f) * w.y;
        s += fmaxf(fmaf(a.z, dinv, b.z), 0.0f) * w.z;
        s += fmaxf(fmaf(a.w, dinv, b.w), 0.0f) * w.w;
    }
    float v = s * dinv;
    g_s1[i] = v;
    g_s2[i] = v;
}

// ---------- scalar scatter ----------
__global__ void k_scatter2(const void* ei, int e) {
    int i = blockIdx.x * blockDim.x + threadIdx.x;
    if (i >= e) return;
    int is64 = g_is64;
    int src = edge_at(ei, is64, (size_t)i);
    int dst = edge_at(ei, is64, (size_t)e + i);
    atomicAdd(&g_s2[dst], g_s1[src]);
}

// ---------- finalize: h2 = acc2*dinv + b2 ; out = relu(h2*Wm1+bm1) . Wm2 + bm2 ----------
__global__ void k_final(const float* __restrict__ b2,
                        const float* __restrict__ Wm1,
                        const float* __restrict__ bm1,
                        const float* __restrict__ Wm2,
                        const float* __restrict__ bm2,
                        float* __restrict__ out, int n) {
    int i = blockIdx.x * blockDim.x + threadIdx.x;
    if (i >= n) return;
    float h2 = fmaf(g_s2[i], rsqrtf(g_deg[i]), __ldg(b2));
    const float4* w1 = reinterpret_cast<const float4*>(Wm1);
    const float4* bb = reinterpret_cast<const float4*>(bm1);
    const float4* w2 = reinterpret_cast<const float4*>(Wm2);
    float s = __ldg(bm2);
#pragma unroll
    for (int j4 = 0; j4 < HID / 4; j4++) {
        float4 a = __ldg(&w1[j4]);
        float4 b = __ldg(&bb[j4]);
        float4 c = __ldg(&w2[j4]);
        s += fmaxf(fmaf(h2, a.x, b.x), 0.0f) * c.x;
        s += fmaxf(fmaf(h2, a.y, b.y), 0.0f) * c.y;
        s += fmaxf(fmaf(h2, a.z, b.z), 0.0f) * c.z;
        s += fmaxf(fmaf(h2, a.w, b.w), 0.0f) * c.w;
    }
    out[i] = s;
}

extern "C" void kernel_launch(void* const* d_in, const int* in_sizes, int n_in,
                              void* d_out, int out_size) {
    const float* x   = (const float*)d_in[0];
    const void*  ei  = d_in[1];
    const float* W0  = (const float*)d_in[2];
    const float* b0  = (const float*)d_in[3];
    const float* W1  = (const float*)d_in[4];
    const float* b1  = (const float*)d_in[5];
    const float* W2  = (const float*)d_in[6];
    const float* b2  = (const float*)d_in[7];
    const float* Wm1 = (const float*)d_in[8];
    const float* bm1 = (const float*)d_in[9];
    const float* Wm2 = (const float*)d_in[10];
    const float* bm2 = (const float*)d_in[11];
    float* out = (float*)d_out;

    int n = in_sizes[0] / FIN;   // 100000
    int e = in_sizes[1] / 2;     // 1200000

    k_detect<<<1, 32>>>((const long long*)ei, e);
    k_deg_init<<<(n + 255) / 256, 256>>>(n);
    k_deg_count<<<(e + 255) / 256, 256>>>(ei, e);

    // layer 0
    k_gemm<FIN, false><<<(n + 127) / 128, 128>>>(x, W0, nullptr, n);
    {
        long long tot = (long long)e * 16;
        k_scatter<<<(unsigned)((tot + 255) / 256), 256>>>(ei, e);
    }
    // layer 1 (fused relu(acc*dinv + b0) on input)
    k_gemm<HID, true><<<(n + 127) / 128, 128>>>(nullptr, W1, b0, n);
    {
        long long tot = (long long)e * 16;
        k_scatter<<<(unsigned)((tot + 255) / 256), 256>>>(ei, e);
    }
    // layer 2 (scalar output) + scatter
    k_gemm2<<<(n + 255) / 256, 256>>>(b1, W2, n);
    k_scatter2<<<(e + 255) / 256, 256>>>(ei, e);
    // finalize + MLP head
    k_final<<<(n + 255) / 256, 256>>>(b2, Wm1, bm1, Wm2, bm2, out, n);
}